// round 17
// baseline (speedup 1.0000x reference)
#include <cuda_runtime.h>
#include <math.h>

// Problem constants: N=8, S=8192, C=1, K=1024, V=64
#define NS_TOTAL 65536
#define VDIM 64
#define KCW 1024
#define BM 64                  // rows per CTA (16 per warp)
#define BK 128
#define NCHUNK (KCW / BK)      // 8
#define GRID 1024
#define THREADS 128

#define XST 132                // x stride: 2*BM + 4 (16B-aligned rows)
#define EST 132                // e stride: BK + 4 — MULTIPLE OF 4 so the
                               // swizzled LDS.128 e-loads stay 16B-aligned (R16 fix)
#define XS_FLOATS (VDIM * XST) // 8448
#define ES_FLOATS (VDIM * EST) // 8448
#define SMEM_BYTES ((XS_FLOATS + ES_FLOATS + KCW + BM) * 4)   // 71936 B -> 3 CTAs/SM

typedef unsigned long long ull;

__device__ float g_en[KCW];
__device__ int   g_counts[KCW];   // zero at load; last CTA re-zeroes each run
__device__ int   g_done;          // zero at load; last CTA resets each run

// Packed fp32x2 ops — IEEE rn per 32-bit lane. Keep register demand under the
// launch-bounds cap (168) or ptxas splits to scalar FFMA (R12 lesson).
__device__ __forceinline__ ull ffma2(ull a, ull b, ull c) {
    ull d;
    asm("fma.rn.f32x2 %0, %1, %2, %3;" : "=l"(d) : "l"(a), "l"(b), "l"(c));
    return d;
}
__device__ __forceinline__ ull fmul2(ull a, ull b) {
    ull d;
    asm("mul.rn.f32x2 %0, %1, %2;" : "=l"(d) : "l"(a), "l"(b));
    return d;
}
__device__ __forceinline__ ull fadd2(ull a, ull b) {
    ull d;
    asm("add.rn.f32x2 %0, %1, %2;" : "=l"(d) : "l"(a), "l"(b));
    return d;
}
__device__ __forceinline__ void unpack2(ull v, float& lo, float& hi) {
    unsigned int l, h;
    asm("mov.b64 {%0, %1}, %2;" : "=r"(l), "=r"(h) : "l"(v));
    lo = __uint_as_float(l);
    hi = __uint_as_float(h);
}
__device__ __forceinline__ ull pack2(float lo, float hi) {
    ull v;
    asm("mov.b64 %0, {%1, %2};" : "=l"(v) : "f"(lo), "f"(hi));
    return v;
}

// e-tile bank swizzle: float-index idx -> idx ^ (4*((v>>2)&7)).
// Touches float-idx bits [2..4] only: 4-float blocks preserved (16B alignment
// + within-block cw order intact). At EST=132: stores 8-way -> 2-way conflicts;
// loads conflict-free (128 consecutive floats XOR-permuted in 16-float blocks).
#define ESWZ(v) (4 * (((v) >> 2) & 7))

// ---------------------------------------------------------------------------
// Kernel 1: codeword norms via coalesced smem staging (bit-exact sequential).
// ---------------------------------------------------------------------------
__global__ void vq_prep_kernel(const float* __restrict__ emb) {
    __shared__ float se[64 * 65];
    const int tid = threadIdx.x;
    const int kb  = blockIdx.x * 64;
    const float4* e4 = reinterpret_cast<const float4*>(emb) + (size_t)kb * (VDIM / 4);
    #pragma unroll
    for (int t = 0; t < 4; t++) {
        int idx = tid + t * 256;           // 1024 float4
        int r   = idx >> 4;
        int v4  = idx & 15;
        float4 f = e4[idx];
        float* d = se + r * 65 + v4 * 4;
        d[0] = f.x; d[1] = f.y; d[2] = f.z; d[3] = f.w;
    }
    __syncthreads();
    if (tid < 64) {
        const float* er = se + tid * 65;
        float acc = 0.0f;
        #pragma unroll 8
        for (int v = 0; v < VDIM; v++)
            acc = __fadd_rn(acc, __fmul_rn(er[v], er[v]));
        g_en[kb + tid] = acc;
    }
}

// ---------------------------------------------------------------------------
// Kernel 2: fused GEMM + argmin + histogram + outputs + (last CTA) entropy
// grid 1024 (64 samples each), 128 threads, 3 CTAs/SM (cap 168)
// thread tile: 16 contiguous rows (warp-owned) x 4 contiguous codewords
// ---------------------------------------------------------------------------
__global__ __launch_bounds__(THREADS, 3)
void vq_main_kernel(const float* __restrict__ x, const float* __restrict__ emb,
                    float* __restrict__ out0, float* __restrict__ out1,
                    float* __restrict__ out2, float* __restrict__ ent) {
    extern __shared__ float sm[];
    float* xs2  = sm;                          // [VDIM][XST] duplicated x pairs
    float* es   = sm + XS_FLOATS;              // [VDIM][EST] e chunk (transposed, swizzled)
    float* en_s = sm + XS_FLOATS + ES_FLOATS;  // [KCW] codeword norms
    float* xn_s = en_s + KCW;                  // [BM] row norms
    // post-loop overlays on es:
    int*   amin_s  = (int*)es;                 // [BM]
    float* rowsum  = es + BM;                  // [BM]

    const int tid  = threadIdx.x;
    const int lane = tid & 31;                 // covers cw 4*lane .. 4*lane+3
    const int wrp  = tid >> 5;                 // 4 warps: rows 16*wrp .. 16*wrp+15
    const int row0 = blockIdx.x * BM;

    // ---- load x tile (coalesced float4), store duplicated pairs (v-major) ----
    const float4* x4 = reinterpret_cast<const float4*>(x) + (size_t)row0 * (VDIM / 4);
    #pragma unroll
    for (int t = 0; t < 8; t++) {
        int lin4 = tid + t * THREADS;          // 1024 float4
        int r    = lin4 >> 4;
        int v4   = lin4 & 15;
        float4 val = x4[lin4];
        *reinterpret_cast<float2*>(xs2 + (v4 * 4 + 0) * XST + 2 * r) = make_float2(val.x, val.x);
        *reinterpret_cast<float2*>(xs2 + (v4 * 4 + 1) * XST + 2 * r) = make_float2(val.y, val.y);
        *reinterpret_cast<float2*>(xs2 + (v4 * 4 + 2) * XST + 2 * r) = make_float2(val.z, val.z);
        *reinterpret_cast<float2*>(xs2 + (v4 * 4 + 3) * XST + 2 * r) = make_float2(val.w, val.w);
    }
    // ---- copy codeword norms into smem (8 per thread) ----
    #pragma unroll
    for (int t = 0; t < 8; t++) en_s[tid + t * THREADS] = g_en[tid + t * THREADS];
    __syncthreads();

    // ---- row norms ||x_r||^2 (sequential mul+add, v ascending) ----
    if (tid < BM) {
        float acc = 0.0f;
        const float* xr = xs2 + 2 * tid;
        #pragma unroll 8
        for (int v = 0; v < VDIM; v++) {
            float xv = xr[v * XST];
            acc = __fadd_rn(acc, __fmul_rn(xv, xv));
        }
        xn_s[tid] = acc;
    }

    float minv[16];
    int   mini[16];
    #pragma unroll
    for (int i = 0; i < 16; i++) { minv[i] = 3.402823466e38f; mini[i] = 0; }

    const ull NEG2 = 0xC0000000C0000000ULL;    // {-2.0f, -2.0f}
    const int txk4 = 4 * lane;

    // thread: rows r_i = 16*wrp + i (i<16), codewords k = c*128 + 4*lane + {0..3}
    for (int c = 0; c < NCHUNK; c++) {
        if (c > 0) __syncthreads();            // compute done before overwriting es
        const float4* e4 = reinterpret_cast<const float4*>(emb) + (size_t)c * (BK * VDIM / 4);
        #pragma unroll 4
        for (int t = 0; t < 16; t++) {
            int lin4 = tid + t * THREADS;      // 2048 float4
            int k    = lin4 >> 4;
            int v4   = lin4 & 15;
            float4 val = e4[lin4];
            int swz = 4 * (v4 & 7);            // ESWZ(4*v4+j) == ESWZ(4*v4)
            es[(((v4 * 4 + 0) * EST + k)) ^ swz] = val.x;
            es[(((v4 * 4 + 1) * EST + k)) ^ swz] = val.y;
            es[(((v4 * 4 + 2) * EST + k)) ^ swz] = val.z;
            es[(((v4 * 4 + 3) * EST + k)) ^ swz] = val.w;
        }
        __syncthreads();

        ull acc[16][2];
        #pragma unroll
        for (int i = 0; i < 16; i++) { acc[i][0] = 0ULL; acc[i][1] = 0ULL; }

        // sequential FMA over v=0..63, single accumulator per (row, codeword)
        #pragma unroll 4
        for (int v = 0; v < VDIM; v++) {
            int ei = (v * EST + txk4) ^ ESWZ(v);   // ≡0 mod 4 -> 16B aligned
            ulonglong2 eq = *reinterpret_cast<const ulonglong2*>(es + ei);
            // x: 16 contiguous duplicated pairs, warp-uniform broadcast LDS.128
            const ulonglong2* xvp =
                reinterpret_cast<const ulonglong2*>(xs2 + v * XST + wrp * 32);
            #pragma unroll
            for (int j = 0; j < 8; j++) {
                ulonglong2 q = xvp[j];
                acc[2 * j][0]     = ffma2(q.x, eq.x, acc[2 * j][0]);
                acc[2 * j][1]     = ffma2(q.x, eq.y, acc[2 * j][1]);
                acc[2 * j + 1][0] = ffma2(q.y, eq.x, acc[2 * j + 1][0]);
                acc[2 * j + 1][1] = ffma2(q.y, eq.y, acc[2 * j + 1][1]);
            }
        }

        // score = fl( fl( xn - fl(2*dot) ) + en ) via packed ops (exact per lane)
        #pragma unroll
        for (int m = 0; m < 2; m++) {
            int k0 = c * BK + txk4 + 2 * m;    // global codeword pair base
            ull en2 = *reinterpret_cast<const ull*>(en_s + k0);
            #pragma unroll
            for (int i = 0; i < 16; i++) {
                float xnv = xn_s[16 * wrp + i];
                ull s2 = fadd2(fadd2(pack2(xnv, xnv), fmul2(acc[i][m], NEG2)), en2);
                float s0, s1;
                unpack2(s2, s0, s1);
                if (s0 < minv[i]) { minv[i] = s0; mini[i] = k0; }
                if (s1 < minv[i]) { minv[i] = s1; mini[i] = k0 + 1; }
            }
        }
    }

    // ---- warp-local argmin reduction (all candidates for a row are in-warp) ----
    #pragma unroll
    for (int i = 0; i < 16; i++) {
        float bv = minv[i];
        int   bi = mini[i];
        #pragma unroll
        for (int off = 16; off > 0; off >>= 1) {
            float ov = __shfl_down_sync(0xffffffffu, bv, off);
            int   oi = __shfl_down_sync(0xffffffffu, bi, off);
            if (ov < bv || (ov == bv && oi < bi)) { bv = ov; bi = oi; }
        }
        mini[i] = bi;
    }
    __syncthreads();                           // all es reads done before overlay writes
    if (lane == 0) {
        #pragma unroll
        for (int i = 0; i < 16; i++) {
            int r = 16 * wrp + i;
            amin_s[r] = mini[i];
            rowsum[r] = 0.0f;
            atomicAdd(&g_counts[mini[i]], 1);
        }
    }
    __syncthreads();

    // ---- outputs: out0 = fl(fl(o - x) + x), out1 = out2 = sum_v (x-o)^2 ----
    #pragma unroll 4
    for (int t = 0; t < 32; t++) {
        int i = t * THREADS + tid;             // 4096 elements; warp = half a row
        int r = i >> 6;
        int v = i & 63;
        float o  = emb[amin_s[r] * VDIM + v];
        float xv = xs2[v * XST + 2 * r];
        float d  = __fsub_rn(xv, o);
        float sq = __fmul_rn(d, d);
        #pragma unroll
        for (int off = 16; off > 0; off >>= 1)
            sq += __shfl_down_sync(0xffffffffu, sq, off);
        if (lane == 0) atomicAdd(&rowsum[r], sq);   // 2 adds/row: order-invariant
        out0[(size_t)(row0 + r) * VDIM + v] = __fadd_rn(__fsub_rn(o, xv), xv);
    }
    __syncthreads();
    if (tid < BM) {
        float s = rowsum[tid];
        out1[row0 + tid] = s;
        out2[row0 + tid] = s;
    }

    // ---- last CTA computes entropy and resets state for the next replay ----
    __threadfence();                           // order this CTA's atomics/stores
    __shared__ int is_last;
    __syncthreads();
    if (tid == 0) {
        int d = atomicAdd(&g_done, 1);
        is_last = (d == GRID - 1);
    }
    __syncthreads();
    if (is_last) {
        // 128 threads x 8 bins each
        float term = 0.0f;
        #pragma unroll
        for (int t = 0; t < 8; t++) {
            int k = tid + t * THREADS;
            int c = g_counts[k];
            g_counts[k] = 0;
            if (c > 0) {
                float p = (float)c * (1.0f / 65536.0f);
                term -= p * logf(p);
            }
        }
        #pragma unroll
        for (int off = 16; off > 0; off >>= 1)
            term += __shfl_down_sync(0xffffffffu, term, off);
        float* wsum = rowsum;                  // reuse smem
        if (lane == 0) wsum[wrp] = term;
        __syncthreads();
        if (tid == 0) {
            float s = 0.0f;
            #pragma unroll
            for (int wI = 0; wI < 4; wI++) s += wsum[wI];
            *ent = s;
            g_done = 0;
        }
    }
}

// ---------------------------------------------------------------------------
extern "C" void kernel_launch(void* const* d_in, const int* in_sizes, int n_in,
                              void* d_out, int out_size) {
    const float* x;
    const float* emb;
    if (in_sizes[0] == NS_TOTAL * VDIM) {
        x   = (const float*)d_in[0];
        emb = (const float*)d_in[1];
    } else {
        x   = (const float*)d_in[1];
        emb = (const float*)d_in[0];
    }

    float* out0 = (float*)d_out;                        // 65536*64
    float* out1 = out0 + (size_t)NS_TOTAL * VDIM;       // 65536
    float* out2 = out1 + NS_TOTAL;                      // 65536
    float* ent  = out2 + NS_TOTAL;                      // 1

    cudaFuncSetAttribute(vq_main_kernel,
                         cudaFuncAttributeMaxDynamicSharedMemorySize, SMEM_BYTES);

    vq_prep_kernel<<<16, 256>>>(emb);
    vq_main_kernel<<<GRID, THREADS, SMEM_BYTES>>>(x, emb, out0, out1, out2, ent);
}